// round 14
// baseline (speedup 1.0000x reference)
#include <cuda_runtime.h>
#include <stdint.h>

#define BTOT   65536
#define NF     256
#define NT     256
#define NC     4
#define TILE_R 32
#define NITERS (BTOT / TILE_R)   // 2048
#define THREADS 1024

// shared-memory byte offsets (total 229376)
#define OFF_ROOT 0            // int2[256]    2048 B
#define OFF_L1   2048         // int2[512]    4096 B
#define OFF_L2   6144         // int2[1024]   8192 B
#define OFF_L3   14336        // int2[2048]  16384 B
#define OFF_L4   30720        // int2[4096]  32768 B
#define OFF_XT   63488        // float[2][8192] transposed x tiles [f][32] 65536 B
#define OFF_XTMP 129024       // float[8192]  row-major cp.async staging   32768 B
#define OFF_SCR  161792       // float4[4*1056] leaf quad staging (pad 33) 67584 B
                              //   overlaid by u64[4224] argmax partials at tile tail
#define SMEM_BYTES 229376

__device__ int2 g_l5[8192];   // packed level-5 {feat, bias-bits}; packed in-kernel

extern __shared__ unsigned char smem_raw[];

__device__ __forceinline__ unsigned fmap(float f) {
    unsigned u = __float_as_uint(f);
    return (u & 0x80000000u) ? ~u : (u | 0x80000000u);
}

__device__ __forceinline__ void cp_async16(void* smem_dst, const void* gmem_src) {
    unsigned saddr = (unsigned)__cvta_generic_to_shared(smem_dst);
    asm volatile("cp.async.cg.shared.global [%0], [%1], 16;" :: "r"(saddr), "l"(gmem_src));
}

__global__ void __launch_bounds__(THREADS, 1)
tree_kernel(const float*  __restrict__ x,
            const int*    __restrict__ rn, const float* __restrict__ rb,
            const float4* __restrict__ leaf,
            const int* __restrict__ n1, const float* __restrict__ b1,
            const int* __restrict__ n2, const float* __restrict__ b2,
            const int* __restrict__ n3, const float* __restrict__ b3,
            const int* __restrict__ n4, const float* __restrict__ b4,
            const int* __restrict__ n5, const float* __restrict__ b5,
            float*  __restrict__ out_amax,     // may be null
            float4* __restrict__ out_vals,
            int nb)
{
    int2*   s_root = (int2*)  (smem_raw + OFF_ROOT);
    int2*   s1     = (int2*)  (smem_raw + OFF_L1);
    int2*   s2     = (int2*)  (smem_raw + OFF_L2);
    int2*   s3     = (int2*)  (smem_raw + OFF_L3);
    int2*   s4     = (int2*)  (smem_raw + OFF_L4);
    float*  sxT    = (float*) (smem_raw + OFF_XT);     // [f][r], double-buffered
    float*  sxtmp  = (float*) (smem_raw + OFF_XTMP);   // row-major staging
    float4* sscr   = (float4*)(smem_raw + OFF_SCR);    // 4 slots of 1056 float4
    unsigned long long* samx = (unsigned long long*)(smem_raw + OFF_SCR); // tail overlay

    const int tid  = threadIdx.x;
    const int w    = tid >> 5;     // warp = tree slot (gather) / row (writeback, argmax)
    const int lane = tid & 31;

    // ---- pack l5 table (idempotent across CTAs; own writes visible after barrier) ----
    for (int i = tid; i < 8192; i += THREADS)
        g_l5[i] = make_int2(n5[i], __float_as_int(b5[i]));

    for (int i = tid; i < 256;  i += THREADS) s_root[i] = make_int2(rn[i], __float_as_int(rb[i]));
    for (int i = tid; i < 512;  i += THREADS) s1[i] = make_int2(n1[i], __float_as_int(b1[i]));
    for (int i = tid; i < 1024; i += THREADS) s2[i] = make_int2(n2[i], __float_as_int(b2[i]));
    for (int i = tid; i < 2048; i += THREADS) s3[i] = make_int2(n3[i], __float_as_int(b3[i]));
    for (int i = tid; i < 4096; i += THREADS) s4[i] = make_int2(n4[i], __float_as_int(b4[i]));

    // ---- prologue: stage + transpose first x tile into sxT[0] ----
    int it = blockIdx.x;
    if (it < NITERS) {
        const float4* xb4 = (const float4*)(x + (size_t)it * (TILE_R * NF));
        ((float4*)sxtmp)[tid]        = xb4[tid];
        ((float4*)sxtmp)[tid + 1024] = xb4[tid + 1024];
    }
    __syncthreads();
    if (it < NITERS) {
        #pragma unroll
        for (int j = 0; j < 8; j++) {            // diagonal transpose, conflict-free
            int f = (j << 5) | lane;
            int r = (lane + w) & 31;
            sxT[f * 32 + r] = sxtmp[r * 256 + f];
        }
    }
    __syncthreads();

    int xbuf = 0;

    for (; it < NITERS; it += nb) {
        const int rowbase = it * TILE_R;
        const int nextit  = it + nb;

        // prefetch next tile's x into sxtmp (overlaps walk + leaf round 0)
        if (nextit < NITERS) {
            const float4* xb4 = (const float4*)(x + (size_t)nextit * (TILE_R * NF));
            cp_async16(((float4*)sxtmp) + tid,        xb4 + tid);
            cp_async16(((float4*)sxtmp) + tid + 1024, xb4 + tid + 1024);
        }
        asm volatile("cp.async.commit_group;");

        float bf0 = -3.0e38f, bf1 = -3.0e38f, bf2 = -3.0e38f, bf3 = -3.0e38f;
        int   bi0 = 0, bi1 = 0, bi2 = 0, bi3 = 0;
        const float* xc = sxT + xbuf * 8192;      // read addr f*32+lane -> bank==lane

        #pragma unroll
        for (int j = 0; j < 2; j++) {
            // four interleaved walk chains: trees j*128 + c*32 + w, c=0..3
            unsigned p[4];
            int2 e[4];
            #pragma unroll
            for (int c = 0; c < 4; c++) {
                const int t = (j << 7) + (c << 5) + w;
                e[c] = s_root[t];
                p[c] = (unsigned)(t << 1) + (xc[(e[c].x << 5) + lane] >= __int_as_float(e[c].y));
            }
            #pragma unroll
            for (int c = 0; c < 4; c++) e[c] = s1[p[c]];
            #pragma unroll
            for (int c = 0; c < 4; c++) p[c] = (p[c] << 1) + (xc[(e[c].x << 5) + lane] >= __int_as_float(e[c].y));
            #pragma unroll
            for (int c = 0; c < 4; c++) e[c] = s2[p[c]];
            #pragma unroll
            for (int c = 0; c < 4; c++) p[c] = (p[c] << 1) + (xc[(e[c].x << 5) + lane] >= __int_as_float(e[c].y));
            #pragma unroll
            for (int c = 0; c < 4; c++) e[c] = s3[p[c]];
            #pragma unroll
            for (int c = 0; c < 4; c++) p[c] = (p[c] << 1) + (xc[(e[c].x << 5) + lane] >= __int_as_float(e[c].y));
            #pragma unroll
            for (int c = 0; c < 4; c++) e[c] = s4[p[c]];
            #pragma unroll
            for (int c = 0; c < 4; c++) p[c] = (p[c] << 1) + (xc[(e[c].x << 5) + lane] >= __int_as_float(e[c].y));
            #pragma unroll
            for (int c = 0; c < 4; c++) e[c] = __ldg(g_l5 + p[c]);
            #pragma unroll
            for (int c = 0; c < 4; c++) p[c] = (p[c] << 1) + (xc[(e[c].x << 5) + lane] >= __int_as_float(e[c].y));

            if (j > 0) __syncthreads();           // previous round's staging reads done

            #pragma unroll
            for (int c = 0; c < 4; c++) {
                const float4 lv = __ldg(leaf + p[c]);
                const int t = (j << 7) + (c << 5) + w;
                if (lv.x > bf0) { bf0 = lv.x; bi0 = t; }   // strict > keeps first (t ascending)
                if (lv.y > bf1) { bf1 = lv.y; bi1 = t; }
                if (lv.z > bf2) { bf2 = lv.z; bi2 = t; }
                if (lv.w > bf3) { bf3 = lv.w; bi3 = t; }
                sscr[c * 1056 + w * 33 + lane] = lv;
            }

            if (j == 0)                            // all threads: own cp.asyncs done BEFORE barrier
                asm volatile("cp.async.wait_group 0;");
            __syncthreads();                       // staging visible + ALL threads' cp.asyncs landed

            if (j == 0 && nextit < NITERS) {
                // transpose next tile into the OTHER xT buffer — safe after barrier,
                // no readers of xT[buf^1] until next tile (beyond tail syncs)
                float* xn = sxT + (xbuf ^ 1) * 8192;
                #pragma unroll
                for (int k = 0; k < 8; k++) {
                    int f = (k << 5) | lane;
                    int r = (lane + w) & 31;
                    xn[f * 32 + r] = sxtmp[r * 256 + f];
                }
            }

            float4* op = out_vals + (size_t)(rowbase + w) * NT + (j << 7) + lane;
            #pragma unroll
            for (int c = 0; c < 4; c++)
                op[c << 5] = sscr[c * 1056 + lane * 33 + w];
        }

        // ---- tile tail ----
        __syncthreads();                       // all sscr reads done -> overlay safe
        if (out_amax) {
            samx[lane * 132 + 0 * 33 + w] = ((unsigned long long)fmap(bf0) << 32) | (unsigned)(255 - bi0);
            samx[lane * 132 + 1 * 33 + w] = ((unsigned long long)fmap(bf1) << 32) | (unsigned)(255 - bi1);
            samx[lane * 132 + 2 * 33 + w] = ((unsigned long long)fmap(bf2) << 32) | (unsigned)(255 - bi2);
            samx[lane * 132 + 3 * 33 + w] = ((unsigned long long)fmap(bf3) << 32) | (unsigned)(255 - bi3);
        }
        __syncthreads();                       // samx visible

        if (out_amax) {                        // warp w reduces row w, classes 0..3
            #pragma unroll
            for (int c = 0; c < 4; c++) {
                unsigned long long bk = samx[w * 132 + c * 33 + lane];
                #pragma unroll
                for (int off = 16; off; off >>= 1) {
                    unsigned long long o = __shfl_down_sync(0xFFFFFFFFu, bk, off);
                    if (o > bk) bk = o;
                }
                if (lane == 0)
                    out_amax[(size_t)(rowbase + w) * NC + c] =
                        (float)(255 - (int)(bk & 0xFFFFFFFFull));
            }
        }
        __syncthreads();                       // samx free + sxtmp free for next cp.async
        xbuf ^= 1;
    }
}

extern "C" void kernel_launch(void* const* d_in, const int* in_sizes, int n_in,
                              void* d_out, int out_size)
{
    const float*  x    = (const float*) d_in[0];
    const int*    rn   = (const int*)   d_in[1];
    const float*  rb   = (const float*) d_in[2];
    const float4* leaf = (const float4*)d_in[3];
    const int*   n1 = (const int*)d_in[4];   const float* b1 = (const float*)d_in[5];
    const int*   n2 = (const int*)d_in[6];   const float* b2 = (const float*)d_in[7];
    const int*   n3 = (const int*)d_in[8];   const float* b3 = (const float*)d_in[9];
    const int*   n4 = (const int*)d_in[10];  const float* b4 = (const float*)d_in[11];
    const int*   n5 = (const int*)d_in[12];  const float* b5 = (const float*)d_in[13];

    const int vals_n = BTOT * NT * NC;
    const int amax_n = BTOT * NC;

    float*  out_amax = 0;
    float4* out_vals;
    if (out_size == vals_n + amax_n) {
        out_amax = (float*)d_out;
        out_vals = (float4*)((float*)d_out + amax_n);
    } else {
        out_vals = (float4*)d_out;
    }

    int dev = 0, sms = 148;
    cudaGetDevice(&dev);
    cudaDeviceGetAttribute(&sms, cudaDevAttrMultiProcessorCount, dev);
    if (sms <= 0) sms = 148;

    cudaFuncSetAttribute(tree_kernel,
                         cudaFuncAttributeMaxDynamicSharedMemorySize, SMEM_BYTES);

    tree_kernel<<<sms, THREADS, SMEM_BYTES>>>(
        x, rn, rb, leaf,
        n1, b1, n2, b2, n3, b3, n4, b4, n5, b5,
        out_amax, out_vals, sms);
}

// round 15
// speedup vs baseline: 1.6212x; 1.6212x over previous
#include <cuda_runtime.h>
#include <stdint.h>

#define BTOT   65536
#define NF     256
#define NT     256
#define NC     4
#define TILE_R 32
#define NITERS (BTOT / TILE_R)   // 2048
#define THREADS 1024

// shared-memory byte offsets (total 196608)
#define OFF_ROOT 0            // int2[256]    2048 B
#define OFF_L1   2048         // int2[512]    4096 B
#define OFF_L2   6144         // int2[1024]   8192 B
#define OFF_L3   14336        // int2[2048]  16384 B
#define OFF_L4   30720        // int2[4096]  32768 B
#define OFF_XT   63488        // float[8192]  transposed x tile [f][32]    32768 B
#define OFF_XTMP 96256        // float[8192]  row-major cp.async staging   32768 B
#define OFF_SCR  129024       // float4[4*1056] leaf quad staging (pad 33) 67584 B
                              //   overlaid by u64[4224] argmax partials at tile tail
#define SMEM_BYTES 196608

__device__ int2 g_l5[8192];   // packed level-5 {feat, bias-bits}

extern __shared__ unsigned char smem_raw[];

__device__ __forceinline__ unsigned fmap(float f) {
    unsigned u = __float_as_uint(f);
    return (u & 0x80000000u) ? ~u : (u | 0x80000000u);
}

__device__ __forceinline__ void cp_async16(void* smem_dst, const void* gmem_src) {
    unsigned saddr = (unsigned)__cvta_generic_to_shared(smem_dst);
    asm volatile("cp.async.cg.shared.global [%0], [%1], 16;" :: "r"(saddr), "l"(gmem_src));
}

__global__ void pack_l5_kernel(const int* __restrict__ n5, const float* __restrict__ b5) {
    int i = blockIdx.x * blockDim.x + threadIdx.x;
    if (i < 8192) g_l5[i] = make_int2(n5[i], __float_as_int(b5[i]));
}

__global__ void __launch_bounds__(THREADS, 1)
tree_kernel(const float*  __restrict__ x,
            const int*    __restrict__ rn, const float* __restrict__ rb,
            const float4* __restrict__ leaf,
            const int* __restrict__ n1, const float* __restrict__ b1,
            const int* __restrict__ n2, const float* __restrict__ b2,
            const int* __restrict__ n3, const float* __restrict__ b3,
            const int* __restrict__ n4, const float* __restrict__ b4,
            float*  __restrict__ out_amax,     // may be null
            float4* __restrict__ out_vals,
            int nb)
{
    int2*   s_root = (int2*)  (smem_raw + OFF_ROOT);
    int2*   s1     = (int2*)  (smem_raw + OFF_L1);
    int2*   s2     = (int2*)  (smem_raw + OFF_L2);
    int2*   s3     = (int2*)  (smem_raw + OFF_L3);
    int2*   s4     = (int2*)  (smem_raw + OFF_L4);
    float*  sxT    = (float*) (smem_raw + OFF_XT);     // [f][r], single buffer
    float*  sxtmp  = (float*) (smem_raw + OFF_XTMP);   // row-major staging
    float4* sscr   = (float4*)(smem_raw + OFF_SCR);    // 4 slots of 1056 float4
    unsigned long long* samx = (unsigned long long*)(smem_raw + OFF_SCR); // tail overlay

    const int tid  = threadIdx.x;
    const int w    = tid >> 5;     // warp = tree slot (gather) / row (writeback, argmax)
    const int lane = tid & 31;

    for (int i = tid; i < 256;  i += THREADS) s_root[i] = make_int2(rn[i], __float_as_int(rb[i]));
    for (int i = tid; i < 512;  i += THREADS) s1[i] = make_int2(n1[i], __float_as_int(b1[i]));
    for (int i = tid; i < 1024; i += THREADS) s2[i] = make_int2(n2[i], __float_as_int(b2[i]));
    for (int i = tid; i < 2048; i += THREADS) s3[i] = make_int2(n3[i], __float_as_int(b3[i]));
    for (int i = tid; i < 4096; i += THREADS) s4[i] = make_int2(n4[i], __float_as_int(b4[i]));

    // ---- prologue: stage + transpose first x tile into sxT ----
    int it = blockIdx.x;
    if (it < NITERS) {
        const float4* xb4 = (const float4*)(x + (size_t)it * (TILE_R * NF));
        ((float4*)sxtmp)[tid]        = xb4[tid];
        ((float4*)sxtmp)[tid + 1024] = xb4[tid + 1024];
    }
    __syncthreads();
    if (it < NITERS) {
        #pragma unroll
        for (int j = 0; j < 8; j++) {            // diagonal transpose, conflict-free
            int f = (j << 5) | lane;
            int r = (lane + w) & 31;
            sxT[f * 32 + r] = sxtmp[r * 256 + f];
        }
    }
    __syncthreads();

    for (; it < NITERS; it += nb) {
        const int rowbase = it * TILE_R;
        const int nextit  = it + nb;

        // prefetch next tile's x into sxtmp (overlaps the whole gather phase)
        if (nextit < NITERS) {
            const float4* xb4 = (const float4*)(x + (size_t)nextit * (TILE_R * NF));
            cp_async16(((float4*)sxtmp) + tid,        xb4 + tid);
            cp_async16(((float4*)sxtmp) + tid + 1024, xb4 + tid + 1024);
        }
        asm volatile("cp.async.commit_group;");

        float bf0 = -3.0e38f, bf1 = -3.0e38f, bf2 = -3.0e38f, bf3 = -3.0e38f;
        int   bi0 = 0, bi1 = 0, bi2 = 0, bi3 = 0;
        const float* xc = sxT;                    // read addr f*32+lane -> bank==lane

        #pragma unroll
        for (int j = 0; j < 2; j++) {
            // four interleaved walk chains: trees j*128 + c*32 + w, c=0..3
            unsigned p[4];
            int2 e[4];
            #pragma unroll
            for (int c = 0; c < 4; c++) {
                const int t = (j << 7) + (c << 5) + w;
                e[c] = s_root[t];
                p[c] = (unsigned)(t << 1) + (xc[(e[c].x << 5) + lane] >= __int_as_float(e[c].y));
            }
            #pragma unroll
            for (int c = 0; c < 4; c++) e[c] = s1[p[c]];
            #pragma unroll
            for (int c = 0; c < 4; c++) p[c] = (p[c] << 1) + (xc[(e[c].x << 5) + lane] >= __int_as_float(e[c].y));
            #pragma unroll
            for (int c = 0; c < 4; c++) e[c] = s2[p[c]];
            #pragma unroll
            for (int c = 0; c < 4; c++) p[c] = (p[c] << 1) + (xc[(e[c].x << 5) + lane] >= __int_as_float(e[c].y));
            #pragma unroll
            for (int c = 0; c < 4; c++) e[c] = s3[p[c]];
            #pragma unroll
            for (int c = 0; c < 4; c++) p[c] = (p[c] << 1) + (xc[(e[c].x << 5) + lane] >= __int_as_float(e[c].y));
            #pragma unroll
            for (int c = 0; c < 4; c++) e[c] = s4[p[c]];
            #pragma unroll
            for (int c = 0; c < 4; c++) p[c] = (p[c] << 1) + (xc[(e[c].x << 5) + lane] >= __int_as_float(e[c].y));
            #pragma unroll
            for (int c = 0; c < 4; c++) e[c] = __ldg(g_l5 + p[c]);
            #pragma unroll
            for (int c = 0; c < 4; c++) p[c] = (p[c] << 1) + (xc[(e[c].x << 5) + lane] >= __int_as_float(e[c].y));

            if (j > 0) __syncthreads();           // previous round's staging reads done

            #pragma unroll
            for (int c = 0; c < 4; c++) {
                const float4 lv = __ldg(leaf + p[c]);
                const int t = (j << 7) + (c << 5) + w;
                if (lv.x > bf0) { bf0 = lv.x; bi0 = t; }   // strict > keeps first (t ascending)
                if (lv.y > bf1) { bf1 = lv.y; bi1 = t; }
                if (lv.z > bf2) { bf2 = lv.z; bi2 = t; }
                if (lv.w > bf3) { bf3 = lv.w; bi3 = t; }
                sscr[c * 1056 + w * 33 + lane] = lv;
            }
            __syncthreads();
            float4* op = out_vals + (size_t)(rowbase + w) * NT + (j << 7) + lane;
            #pragma unroll
            for (int c = 0; c < 4; c++)
                op[c << 5] = sscr[c * 1056 + lane * 33 + w];
        }

        // ---- tile tail ----
        __syncthreads();                       // all sscr reads done -> overlay safe
        if (out_amax) {
            samx[lane * 132 + 0 * 33 + w] = ((unsigned long long)fmap(bf0) << 32) | (unsigned)(255 - bi0);
            samx[lane * 132 + 1 * 33 + w] = ((unsigned long long)fmap(bf1) << 32) | (unsigned)(255 - bi1);
            samx[lane * 132 + 2 * 33 + w] = ((unsigned long long)fmap(bf2) << 32) | (unsigned)(255 - bi2);
            samx[lane * 132 + 3 * 33 + w] = ((unsigned long long)fmap(bf3) << 32) | (unsigned)(255 - bi3);
        }
        asm volatile("cp.async.wait_group 0;");
        __syncthreads();                       // samx visible + sxtmp landed + gathers done

        if (nextit < NITERS) {                 // transpose next tile into sxT
            #pragma unroll
            for (int j = 0; j < 8; j++) {
                int f = (j << 5) | lane;
                int r = (lane + w) & 31;
                sxT[f * 32 + r] = sxtmp[r * 256 + f];
            }
        }
        if (out_amax) {                        // warp w reduces row w, classes 0..3
            #pragma unroll
            for (int c = 0; c < 4; c++) {
                unsigned long long bk = samx[w * 132 + c * 33 + lane];
                #pragma unroll
                for (int off = 16; off; off >>= 1) {
                    unsigned long long o = __shfl_down_sync(0xFFFFFFFFu, bk, off);
                    if (o > bk) bk = o;
                }
                if (lane == 0)
                    out_amax[(size_t)(rowbase + w) * NC + c] =
                        (float)(255 - (int)(bk & 0xFFFFFFFFull));
            }
        }
        __syncthreads();                       // sxT ready + samx free for next tile
    }
}

extern "C" void kernel_launch(void* const* d_in, const int* in_sizes, int n_in,
                              void* d_out, int out_size)
{
    const float*  x    = (const float*) d_in[0];
    const int*    rn   = (const int*)   d_in[1];
    const float*  rb   = (const float*) d_in[2];
    const float4* leaf = (const float4*)d_in[3];
    const int*   n1 = (const int*)d_in[4];   const float* b1 = (const float*)d_in[5];
    const int*   n2 = (const int*)d_in[6];   const float* b2 = (const float*)d_in[7];
    const int*   n3 = (const int*)d_in[8];   const float* b3 = (const float*)d_in[9];
    const int*   n4 = (const int*)d_in[10];  const float* b4 = (const float*)d_in[11];
    const int*   n5 = (const int*)d_in[12];  const float* b5 = (const float*)d_in[13];

    const int vals_n = BTOT * NT * NC;
    const int amax_n = BTOT * NC;

    float*  out_amax = 0;
    float4* out_vals;
    if (out_size == vals_n + amax_n) {
        out_amax = (float*)d_out;
        out_vals = (float4*)((float*)d_out + amax_n);
    } else {
        out_vals = (float4*)d_out;
    }

    int dev = 0, sms = 148;
    cudaGetDevice(&dev);
    cudaDeviceGetAttribute(&sms, cudaDevAttrMultiProcessorCount, dev);
    if (sms <= 0) sms = 148;

    pack_l5_kernel<<<8, 1024>>>(n5, b5);

    cudaFuncSetAttribute(tree_kernel,
                         cudaFuncAttributeMaxDynamicSharedMemorySize, SMEM_BYTES);

    tree_kernel<<<sms, THREADS, SMEM_BYTES>>>(
        x, rn, rb, leaf,
        n1, b1, n2, b2, n3, b3, n4, b4,
        out_amax, out_vals, sms);
}